// round 13
// baseline (speedup 1.0000x reference)
#include <cuda_runtime.h>
#include <math.h>
#include <stdint.h>

#define N_PTS 65536
#define DIMS  64
#define KCL   128
#define ABLK  128
#define NBLK  (N_PTS / ABLK)      // 512
#define KD    (KCL * DIMS)        // 8192
#define EPSV  1e-8f
#define BIGF  3.402823466e38f
#define RT    512                 // radixL threads
#define NW    (RT / 32)           // 16 warps
#define HALF  16384
#define MT    512                 // merge threads
#define SKW(i) ((i) + ((i) >> 5)) // bank-skewed shared index
#define MBUF  (8192 + 256)        // skewed buffer size (floats)

__device__ int    g_pred[N_PTS];
__device__ int    g_histx[NBLK * KCL];
__device__ int    g_histt[NBLK * KCL];
__device__ float  g_fillp[NBLK * KCL];
__device__ float  g_fill[KCL];
__device__ int    g_m[KCL];
__device__ int    g_P[KCL];
__device__ int    g_off[KCL];
__device__ float  g_part[KD];
__device__ int    g_l1[KCL], g_l2a[KCL], g_l2b[KCL], g_l3[KCL];
__device__ int    g_n1, g_n2a, g_n2b, g_n3;
__device__ float  g_xg[(size_t)(2 * N_PTS) * DIMS];
__device__ float  g_tg[(size_t)(2 * N_PTS) * DIMS];

// ----------------------------------------------------------------------------
// K1: distances, argmin, soft filling, per-block histograms.
// ----------------------------------------------------------------------------
__global__ void k_assign(const float* __restrict__ x, const float* __restrict__ cc,
                         const int* __restrict__ predt) {
    extern __shared__ float dyn[];
    float* sc    = dyn;
    float* scn   = sc + KCL * DIMS;
    float* wca   = scn + KCL;
    float* sfill = wca + KCL * ABLK;
    int*   shx   = (int*)(sfill + KCL);
    int*   sht   = shx + KCL;

    const int tid = threadIdx.x;

    for (int j = tid; j < KCL * DIMS; j += ABLK) sc[j] = cc[j];
    if (tid < KCL) { sfill[tid] = 0.0f; shx[tid] = 0; sht[tid] = 0; }
    __syncthreads();
    if (tid < KCL) {
        float s = 0.0f;
        const float* cp = sc + tid * DIMS;
        #pragma unroll
        for (int d = 0; d < DIMS; d++) s += cp[d] * cp[d];
        scn[tid] = s;
    }
    __syncthreads();

    const int i = blockIdx.x * ABLK + tid;
    float xr[DIMS];
    {
        const float4* xp = (const float4*)(x + (size_t)i * DIMS);
        #pragma unroll
        for (int q = 0; q < 16; q++) {
            float4 v = xp[q];
            xr[4*q] = v.x; xr[4*q+1] = v.y; xr[4*q+2] = v.z; xr[4*q+3] = v.w;
        }
    }
    float xn = 0.0f;
    #pragma unroll
    for (int d = 0; d < DIMS; d++) xn += xr[d] * xr[d];

    float wsum = 0.0f, best = BIGF;
    int bc = 0;
    for (int c = 0; c < KCL; c++) {
        const float4* cp = (const float4*)(sc + c * DIMS);
        float a0 = 0.f, a1 = 0.f, a2 = 0.f, a3 = 0.f;
        #pragma unroll
        for (int q = 0; q < 16; q++) {
            float4 v = cp[q];
            a0 += xr[4*q]   * v.x;
            a1 += xr[4*q+1] * v.y;
            a2 += xr[4*q+2] * v.z;
            a3 += xr[4*q+3] * v.w;
        }
        float dot = (a0 + a1) + (a2 + a3);
        float d2 = xn + scn[c] - 2.0f * dot;
        float dist = sqrtf(fmaxf(d2, 0.0f));
        if (dist < best) { best = dist; bc = c; }
        float w = __fdividef(1.0f, dist + EPSV);
        wca[c * ABLK + tid] = w;
        wsum += w;
    }
    const float inv = __fdividef(1.0f, wsum);
    const int lane = tid & 31;

    for (int c = 0; c < KCL; c++) {
        float w = wca[c * ABLK + tid] * inv;
        #pragma unroll
        for (int o = 16; o > 0; o >>= 1) w += __shfl_down_sync(0xffffffffu, w, o);
        if (lane == 0) atomicAdd(&sfill[c], w);
    }

    g_pred[i] = bc;
    atomicAdd(&shx[bc], 1);
    atomicAdd(&sht[predt[i]], 1);
    __syncthreads();
    if (tid < KCL) {
        g_fillp[blockIdx.x * KCL + tid] = sfill[tid];
        g_histx[blockIdx.x * KCL + tid] = shx[tid];
        g_histt[blockIdx.x * KCL + tid] = sht[tid];
    }
}

// ----------------------------------------------------------------------------
// K2: per-cluster scan of block hists + m, P + fill reduction.
// ----------------------------------------------------------------------------
__global__ void k_scan1() {
    const int c = blockIdx.x;
    const int t = threadIdx.x;
    __shared__ int   s[NBLK];
    __shared__ float sf[NBLK];

    int v = g_histx[t * KCL + c];
    s[t] = v; __syncthreads();
    int acc = v;
    for (int o = 1; o < NBLK; o <<= 1) {
        int add = (t >= o) ? s[t - o] : 0;
        __syncthreads();
        acc += add; s[t] = acc;
        __syncthreads();
    }
    g_histx[t * KCL + c] = acc - v;
    int cntx = s[NBLK - 1];
    __syncthreads();

    v = g_histt[t * KCL + c];
    s[t] = v; __syncthreads();
    acc = v;
    for (int o = 1; o < NBLK; o <<= 1) {
        int add = (t >= o) ? s[t - o] : 0;
        __syncthreads();
        acc += add; s[t] = acc;
        __syncthreads();
    }
    g_histt[t * KCL + c] = acc - v;
    int cntt = s[NBLK - 1];
    __syncthreads();

    sf[t] = g_fillp[t * KCL + c];
    __syncthreads();
    for (int o = NBLK / 2; o > 0; o >>= 1) {
        if (t < o) sf[t] += sf[t + o];
        __syncthreads();
    }

    if (t == 0) {
        g_fill[c] = sf[0];
        int m = min(cntx, cntt);
        g_m[c] = m;
        int P = 0;
        if (m > 0) { P = 1; while (P < m) P <<= 1; }
        g_P[c] = P;
    }
}

// ----------------------------------------------------------------------------
// K3: stable rank + gather both sides; builds g_off and tier work lists.
// ----------------------------------------------------------------------------
__global__ void k_scatter2(const float* __restrict__ x, const float* __restrict__ tgt,
                           const int* __restrict__ predt) {
    __shared__ int cntx[KCL];
    __shared__ int cntt[KCL];
    __shared__ int soff[KCL];
    __shared__ int f1[KCL], f2a[KCL], f2b[KCL], f3[KCL];
    const int tid = threadIdx.x;   // blockDim = 128 = KCL
    cntx[tid] = 0; cntt[tid] = 0;

    const int mC = g_m[tid];
    const int PC = g_P[tid];
    soff[tid] = PC;
    f1[tid]  = (mC >= 2 && PC <= 1024) ? 1 : 0;
    f2a[tid] = (PC >= 2048 && PC <= 8192) ? 1 : 0;
    f2b[tid] = (PC == 16384 || PC == 32768) ? 1 : 0;
    f3[tid]  = (PC > 32768) ? 1 : 0;
    __syncthreads();

    int aoff = soff[tid], a1 = f1[tid], a2a = f2a[tid], a2b = f2b[tid], a3 = f3[tid];
    for (int o = 1; o < KCL; o <<= 1) {
        int b0 = (tid >= o) ? soff[tid - o] : 0;
        int b1 = (tid >= o) ? f1[tid - o]  : 0;
        int b2 = (tid >= o) ? f2a[tid - o] : 0;
        int b3 = (tid >= o) ? f2b[tid - o] : 0;
        int b4 = (tid >= o) ? f3[tid - o]  : 0;
        __syncthreads();
        aoff += b0; a1 += b1; a2a += b2; a2b += b3; a3 += b4;
        soff[tid] = aoff; f1[tid] = a1; f2a[tid] = a2a; f2b[tid] = a2b; f3[tid] = a3;
        __syncthreads();
    }
    soff[tid] = aoff - PC;
    g_off[tid] = soff[tid];
    if (mC >= 2 && PC <= 1024)            g_l1[a1 - 1]  = tid;
    if (PC >= 2048 && PC <= 8192)         g_l2a[a2a - 1] = tid;
    if (PC == 16384 || PC == 32768)       g_l2b[a2b - 1] = tid;
    if (PC > 32768)                       g_l3[a3 - 1]  = tid;
    if (tid == KCL - 1) { g_n1 = a1; g_n2a = a2a; g_n2b = a2b; g_n3 = a3; }
    __syncthreads();

    const int i = blockIdx.x * ABLK + tid;
    const int cx = g_pred[i];
    const int ct = predt[i];
    const int myw = tid >> 5, lane = tid & 31;
    int rx = 0, rt = 0;

    for (int w = 0; w < ABLK / 32; w++) {
        if (myw == w) {
            unsigned peers = __match_any_sync(0xffffffffu, cx);
            unsigned lower = peers & ((1u << lane) - 1u);
            int leader = __ffs(peers) - 1;
            int base = 0;
            if (lane == leader) base = atomicAdd(&cntx[cx], __popc(peers));
            base = __shfl_sync(0xffffffffu, base, leader);
            rx = base + __popc(lower);

            peers = __match_any_sync(0xffffffffu, ct);
            lower = peers & ((1u << lane) - 1u);
            leader = __ffs(peers) - 1;
            base = 0;
            if (lane == leader) base = atomicAdd(&cntt[ct], __popc(peers));
            base = __shfl_sync(0xffffffffu, base, leader);
            rt = base + __popc(lower);
        }
        __syncthreads();
    }

    {
        const int r = g_histx[blockIdx.x * KCL + cx] + rx;
        if (r < g_m[cx]) {
            const int P = g_P[cx];
            float* dst = g_xg + (size_t)soff[cx] * DIMS + r;
            const float4* sp = (const float4*)(x + (size_t)i * DIMS);
            #pragma unroll
            for (int q = 0; q < 16; q++) {
                float4 v = sp[q];
                dst[(size_t)(4*q)     * P] = v.x;
                dst[(size_t)(4*q + 1) * P] = v.y;
                dst[(size_t)(4*q + 2) * P] = v.z;
                dst[(size_t)(4*q + 3) * P] = v.w;
            }
        }
    }
    {
        const int r = g_histt[blockIdx.x * KCL + ct] + rt;
        if (r < g_m[ct]) {
            const int P = g_P[ct];
            float* dst = g_tg + (size_t)soff[ct] * DIMS + r;
            const float4* sp = (const float4*)(tgt + (size_t)i * DIMS);
            #pragma unroll
            for (int q = 0; q < 16; q++) {
                float4 v = sp[q];
                dst[(size_t)(4*q)     * P] = v.x;
                dst[(size_t)(4*q + 1) * P] = v.y;
                dst[(size_t)(4*q + 2) * P] = v.z;
                dst[(size_t)(4*q + 3) * P] = v.w;
            }
        }
    }
}

// ----------------------------------------------------------------------------
// Warp-level in-register bitonic sort, fully unrolled templates.
// ----------------------------------------------------------------------------
template<int R, int JR>
__device__ __forceinline__ void reg_exch(float* v, int k) {
    #pragma unroll
    for (int r = 0; r < R; r++) {
        if ((r & JR) == 0) {
            float a = v[r], b = v[r | JR];
            bool up = (((r << 5) & k) == 0);
            float mn = fminf(a, b), mx = fmaxf(a, b);
            v[r]      = up ? mn : mx;
            v[r | JR] = up ? mx : mn;
        }
    }
}

template<int NE>
__device__ __forceinline__ void warp_sort_reg(float* v, int lane) {
    constexpr int R = NE / 32;
    #pragma unroll
    for (int k = 2; k <= NE; k <<= 1) {
        #pragma unroll
        for (int j = k >> 1; j >= 32; j >>= 1) {
            const int jr = j >> 5;
            if (jr == 1) reg_exch<R, 1>(v, k);
            if constexpr (R >= 4)  { if (jr == 2)  reg_exch<R, (R >= 4 ? 2 : 1)>(v, k); }
            if constexpr (R >= 8)  { if (jr == 4)  reg_exch<R, (R >= 8 ? 4 : 1)>(v, k); }
            if constexpr (R >= 16) { if (jr == 8)  reg_exch<R, (R >= 16 ? 8 : 1)>(v, k); }
            if constexpr (R >= 32) { if (jr == 16) reg_exch<R, (R >= 32 ? 16 : 1)>(v, k); }
        }
        const int j0 = (k >> 1 < 32) ? (k >> 1) : 16;
        #pragma unroll
        for (int j = j0; j >= 1; j >>= 1) {
            #pragma unroll
            for (int r = 0; r < R; r++) {
                int e = (r << 5) | lane;
                float pv = __shfl_xor_sync(0xffffffffu, v[r], j);
                bool desc  = (e & k) != 0;
                bool upper = (lane & j) != 0;
                v[r] = (upper != desc) ? fmaxf(v[r], pv) : fminf(v[r], pv);
            }
        }
    }
}

template<int NE>
__device__ __forceinline__ void warp_sort_seg(float* seg, int m, int lane) {
    constexpr int R = NE / 32;
    float v[R];
    #pragma unroll
    for (int q = 0; q < R; q++) {
        int e = q * 32 + lane;
        v[q] = (e < m) ? seg[e] : BIGF;
    }
    warp_sort_reg<NE>(v, lane);
    #pragma unroll
    for (int q = 0; q < R; q++) {
        int e = q * 32 + lane;
        if (e < m) seg[e] = v[q];
    }
}

// ----------------------------------------------------------------------------
// Merge sort for P in {2048, 4096, 8192}: warp-register 1024-run sorts + skewed
// merge-path rounds in shared (one fewer round than 512-runs).
// smem: A(MBUF) | B(MBUF) floats = 67584 B.
// ----------------------------------------------------------------------------
__global__ void __launch_bounds__(MT)
k_sort_merge() {
    extern __shared__ float sf2[];
    float* bufA = sf2;
    float* bufB = sf2 + MBUF;
    const int tid = threadIdx.x;
    const int w = tid >> 5, lane = tid & 31;
    const int nseg = g_n2a * 128;

    for (int s = blockIdx.x; s < nseg; s += gridDim.x) {
        const int c = g_l2a[s >> 7];
        const int r = s & 127;
        const int d = r & 63;
        const int m = g_m[c], P = g_P[c];
        float* seg = ((r >> 6) ? g_tg : g_xg) + (size_t)g_off[c] * DIMS + (size_t)d * P;

        for (int i = tid; i < P; i += MT)
            bufA[SKW(i)] = (i < m) ? seg[i] : BIGF;
        __syncthreads();

        // phase 1: warp-register sort of 1024-element runs (ascending)
        const int nruns = P >> 10;
        for (int run = w; run < nruns; run += MT / 32) {
            const int rb = run * 1024;
            float v[32];
            #pragma unroll
            for (int q = 0; q < 32; q++) v[q] = bufA[SKW(rb + q * 32 + lane)];
            warp_sort_reg<1024>(v, lane);
            #pragma unroll
            for (int q = 0; q < 32; q++) bufA[SKW(rb + q * 32 + lane)] = v[q];
        }
        __syncthreads();

        // phase 2: merge-path rounds starting at L=1024 (skewed, conflict-free)
        float* src = bufA;
        float* dst = bufB;
        const int G = P >> 9;                 // outputs per thread (4/8/16)
        for (int L = 1024; L < P; L <<= 1) {
            const int k0 = tid * G;
            const int base = k0 & ~(2 * L - 1);
            const int kl = k0 - base;         // diagonal within pair [0, 2L)
            const int aoff = base, boff = base + L;
            int lo = kl - L; if (lo < 0) lo = 0;
            int hi = kl < L ? kl : L;
            while (lo < hi) {
                int mid = (lo + hi) >> 1;
                if (src[SKW(aoff + mid)] <= src[SKW(boff + kl - mid - 1)]) lo = mid + 1;
                else hi = mid;
            }
            int a = lo, b = kl - lo;
            #pragma unroll 4
            for (int o = 0; o < G; o++) {
                float va = (a < L) ? src[SKW(aoff + a)] : BIGF;
                float vb = (b < L) ? src[SKW(boff + b)] : BIGF;
                if (va <= vb) { dst[SKW(k0 + o)] = va; a++; }
                else          { dst[SKW(k0 + o)] = vb; b++; }
            }
            __syncthreads();
            float* t = src; src = dst; dst = t;
        }

        for (int i = tid; i < m; i += MT) seg[i] = src[SKW(i)];
        __syncthreads();
    }
}

// Warp-per-segment: P <= 512 (low regs, high occupancy), NE dispatch.
__global__ void __launch_bounds__(256)
k_sort_warpA() {
    const int lane = threadIdx.x & 31;
    const int gw = (blockIdx.x * 256 + threadIdx.x) >> 5;
    const int nwarps = (gridDim.x * 256) >> 5;
    const int nseg = g_n1 * 128;

    for (int s = gw; s < nseg; s += nwarps) {
        const int c = g_l1[s >> 7];
        const int P = g_P[c];
        if (P > 512) continue;
        const int r = s & 127;
        const int d = r & 63;
        const int m = g_m[c];
        float* seg = ((r >> 6) ? g_tg : g_xg) + (size_t)g_off[c] * DIMS + (size_t)d * P;

        if (P <= 64)        warp_sort_seg<64>(seg, m, lane);
        else if (P == 128)  warp_sort_seg<128>(seg, m, lane);
        else if (P == 256)  warp_sort_seg<256>(seg, m, lane);
        else                warp_sort_seg<512>(seg, m, lane);
    }
}

// Warp-per-segment: P == 1024 (32 data regs).
__global__ void __launch_bounds__(256)
k_sort_warpB() {
    const int lane = threadIdx.x & 31;
    const int gw = (blockIdx.x * 256 + threadIdx.x) >> 5;
    const int nwarps = (gridDim.x * 256) >> 5;
    const int nseg = g_n1 * 128;

    for (int s = gw; s < nseg; s += nwarps) {
        const int c = g_l1[s >> 7];
        const int P = g_P[c];
        if (P != 1024) continue;
        const int r = s & 127;
        const int d = r & 63;
        const int m = g_m[c];
        float* seg = ((r >> 6) ? g_tg : g_xg) + (size_t)g_off[c] * DIMS + (size_t)d * P;
        warp_sort_seg<1024>(seg, m, lane);
    }
}

// ----------------------------------------------------------------------------
// Radix machinery (only for P in {16384, 32768}; measured near-empty)
// ----------------------------------------------------------------------------
__device__ __forceinline__ unsigned f2k(float f) {
    unsigned b = __float_as_uint(f);
    return (b & 0x80000000u) ? ~b : (b | 0x80000000u);
}
__device__ __forceinline__ float k2f(unsigned k) {
    unsigned b = (k & 0x80000000u) ? (k & 0x7FFFFFFFu) : ~k;
    return __uint_as_float(b);
}

__device__ void radix_pass(const unsigned* src, unsigned* dst, unsigned* hist,
                           unsigned* tot, int n, int shift) {
    const int tid = threadIdx.x, w = tid >> 5, l = tid & 31;
    const int E = n / RT;
    const int wbase = w * 32 * E;

    for (int i = tid; i < NW * 256; i += RT) hist[i] = 0;
    __syncthreads();

    for (int e = 0; e < E; e++) {
        unsigned u = src[wbase + e * 32 + l];
        atomicAdd(&hist[w * 256 + ((u >> shift) & 255u)], 1u);
    }
    __syncthreads();

    if (tid < 256) {
        unsigned run = 0;
        #pragma unroll
        for (int ww = 0; ww < NW; ww++) {
            unsigned t = hist[ww * 256 + tid];
            hist[ww * 256 + tid] = run;
            run += t;
        }
        tot[tid] = run;
    }
    __syncthreads();

    if (w == 0) {
        unsigned v[8], lsum = 0;
        #pragma unroll
        for (int q = 0; q < 8; q++) { v[q] = tot[l * 8 + q]; lsum += v[q]; }
        unsigned excl = lsum;
        #pragma unroll
        for (int o = 1; o < 32; o <<= 1) {
            unsigned t = __shfl_up_sync(0xffffffffu, excl, o);
            if (l >= o) excl += t;
        }
        excl -= lsum;
        #pragma unroll
        for (int q = 0; q < 8; q++) {
            unsigned t = v[q];
            tot[l * 8 + q] = excl;
            excl += t;
        }
    }
    __syncthreads();

    for (int i = tid; i < NW * 256; i += RT) hist[i] += tot[i & 255];
    __syncthreads();

    for (int e = 0; e < E; e++) {
        unsigned u = src[wbase + e * 32 + l];
        unsigned d = (u >> shift) & 255u;
        unsigned peers = __match_any_sync(0xffffffffu, d);
        int leader = __ffs(peers) - 1;
        unsigned base = 0;
        if (l == leader) base = hist[w * 256 + d];
        base = __shfl_sync(0xffffffffu, base, leader);
        unsigned rank = base + __popc(peers & ((1u << l) - 1u));
        if (l == leader) hist[w * 256 + d] = base + __popc(peers);
        dst[rank] = u;
    }
    __syncthreads();
}

__device__ void radix_sort_n(unsigned* A, unsigned* PP, unsigned* hist,
                             unsigned* tot, int n) {
    radix_pass(A, PP, hist, tot, n, 0);
    radix_pass(PP, A, hist, tot, n, 8);
    radix_pass(A, PP, hist, tot, n, 16);
    radix_pass(PP, A, hist, tot, n, 24);
}

__device__ void merge_write(const unsigned* A, const unsigned* B, float* out) {
    const int tid = threadIdx.x;
    const int k0 = tid * (2 * HALF / RT);
    int lo = max(0, k0 - HALF), hi = min(k0, HALF);
    while (lo < hi) {
        int mid = (lo + hi) >> 1;
        if (A[mid] <= B[k0 - mid - 1]) lo = mid + 1; else hi = mid;
    }
    int a = lo, b = k0 - lo;
    #pragma unroll 4
    for (int o = 0; o < 2 * HALF / RT; o++) {
        unsigned va = (a < HALF) ? A[a] : 0xFFFFFFFFu;
        unsigned vb = (b < HALF) ? B[b] : 0xFFFFFFFFu;
        unsigned v;
        if (va <= vb) { v = va; a++; } else { v = vb; b++; }
        out[k0 + o] = k2f(v);
    }
}

__global__ void __launch_bounds__(RT)
k_sort_radixL() {
    extern __shared__ unsigned su[];
    unsigned* R0 = su;
    unsigned* R1 = su + HALF;
    unsigned* R2 = su + 2 * HALF;
    unsigned* hist = su + 3 * HALF;
    unsigned* tot = hist + NW * 256;
    const int tid = threadIdx.x;
    const int nseg = g_n2b * 128;

    for (int s = blockIdx.x; s < nseg; s += gridDim.x) {
        const int c = g_l2b[s >> 7];
        const int r = s & 127;
        const int d = r & 63;
        const int m = g_m[c], P = g_P[c];
        float* seg = ((r >> 6) ? g_tg : g_xg) + (size_t)g_off[c] * DIMS + (size_t)d * P;

        if (m <= HALF) {
            const int n = ((m + RT - 1) / RT) * RT;
            for (int i = tid; i < n; i += RT)
                R0[i] = (i < m) ? f2k(seg[i]) : 0xFFFFFFFFu;
            __syncthreads();
            radix_sort_n(R0, R2, hist, tot, n);
            for (int i = tid; i < m; i += RT) seg[i] = k2f(R0[i]);
        } else {
            for (int i = tid; i < HALF; i += RT)
                R0[i] = (i < m) ? f2k(seg[i]) : 0xFFFFFFFFu;
            __syncthreads();
            radix_sort_n(R0, R2, hist, tot, HALF);
            for (int i = tid; i < HALF; i += RT) {
                int j = HALF + i;
                R1[i] = (j < m) ? f2k(seg[j]) : 0xFFFFFFFFu;
            }
            __syncthreads();
            radix_sort_n(R1, R2, hist, tot, HALF);
            merge_write(R0, R1, seg);
        }
        __syncthreads();
    }
}

// Global bitonic fallback, P > 32768 (safety; expected empty)
__global__ void __launch_bounds__(1024)
k_sort_t3() {
    const int T = blockDim.x, tid = threadIdx.x;
    const int nseg = g_n3 * 128;
    for (int s = blockIdx.x; s < nseg; s += gridDim.x) {
        const int c = g_l3[s >> 7];
        const int r = s & 127;
        const int d = r & 63;
        const int m = g_m[c], P = g_P[c];
        float* seg = ((r >> 6) ? g_tg : g_xg) + (size_t)g_off[c] * DIMS + (size_t)d * P;
        for (int j = m + tid; j < P; j += T) seg[j] = BIGF;
        __syncthreads();
        for (int k = 2; k <= P; k <<= 1) {
            for (int j = k >> 1; j > 0; j >>= 1) {
                for (int idx = tid; idx < P; idx += T) {
                    int l = idx ^ j;
                    if (l > idx) {
                        float a = seg[idx], b = seg[l];
                        bool up = ((idx & k) == 0);
                        if ((a > b) == up) { seg[idx] = b; seg[l] = a; }
                    }
                }
                __syncthreads();
            }
        }
        __syncthreads();
    }
}

// ----------------------------------------------------------------------------
// K5: Wasserstein partials per (cluster, dim)
// ----------------------------------------------------------------------------
__global__ void k_diff() {
    const int cd = blockIdx.x;
    const int c = cd >> 6, d = cd & 63;
    const int m = g_m[c];
    if (m < 1) { if (threadIdx.x == 0) g_part[cd] = 0.0f; return; }
    const int P = g_P[c];
    const size_t base = (size_t)g_off[c] * DIMS + (size_t)d * P;

    float s = 0.0f;
    for (int j = threadIdx.x; j < m; j += blockDim.x)
        s += fabsf(g_xg[base + j] - g_tg[base + j]);

    __shared__ float red[256];
    red[threadIdx.x] = s;
    __syncthreads();
    for (int o = blockDim.x >> 1; o > 0; o >>= 1) {
        if (threadIdx.x < o) red[threadIdx.x] += red[threadIdx.x + o];
        __syncthreads();
    }
    if (threadIdx.x == 0)
        g_part[cd] = red[0] / ((float)m * DIMS);
}

// ----------------------------------------------------------------------------
// K6: finalize
// ----------------------------------------------------------------------------
__global__ void k_final(const float* __restrict__ ftgt, float* out) {
    const int tid = threadIdx.x;
    __shared__ double red[256];

    double s = 0.0;
    for (int i = tid; i < KD; i += 256) s += (double)g_part[i];
    red[tid] = s;
    __syncthreads();
    for (int o = 128; o > 0; o >>= 1) {
        if (tid < o) red[tid] += red[tid + o];
        __syncthreads();
    }

    if (tid == 0) {
        float lf = 0.0f;
        for (int c = 0; c < KCL; c++) {
            float diff = g_fill[c] * (1.0f / N_PTS) - ftgt[c];
            lf += diff * diff;
        }
        out[0] = (float)((double)(lf / KCL) + red[0]);
    }
}

// ----------------------------------------------------------------------------
// Launch
// ----------------------------------------------------------------------------
extern "C" void kernel_launch(void* const* d_in, const int* in_sizes, int n_in,
                              void* d_out, int out_size) {
    const float* x     = (const float*)d_in[0];
    const float* tgt   = (const float*)d_in[1];
    const float* cc    = (const float*)d_in[2];
    const int*   predt = (const int*)d_in[3];
    const float* ftgt  = (const float*)d_in[4];
    float* out = (float*)d_out;

    const int ASSIGN_SMEM = (KCL * DIMS + KCL + KCL * ABLK + KCL) * 4 + KCL * 8;
    const int MERGE_SMEM = 2 * MBUF * 4;                     // 67584 B
    const int RADL_SMEM = (3 * HALF + NW * 256 + 256) * 4;   // 214016 B
    cudaFuncSetAttribute(k_assign,
                         cudaFuncAttributeMaxDynamicSharedMemorySize, ASSIGN_SMEM);
    cudaFuncSetAttribute(k_sort_merge,
                         cudaFuncAttributeMaxDynamicSharedMemorySize, MERGE_SMEM);
    cudaFuncSetAttribute(k_sort_radixL,
                         cudaFuncAttributeMaxDynamicSharedMemorySize, RADL_SMEM);

    k_assign<<<NBLK, ABLK, ASSIGN_SMEM>>>(x, cc, predt);     // 0
    k_scan1<<<KCL, NBLK>>>();                                // 1
    k_scatter2<<<NBLK, ABLK>>>(x, tgt, predt);               // 2
    k_sort_merge<<<444, MT, MERGE_SMEM>>>();                 // 3 <- ncu (verify 1024-run)
    k_sort_warpA<<<2048, 256>>>();                           // 4
    k_sort_warpB<<<1024, 256>>>();                           // 5
    k_sort_radixL<<<148, RT, RADL_SMEM>>>();                 // 6
    k_sort_t3<<<148, 1024>>>();                              // 7
    k_diff<<<KD, 256>>>();                                   // 8
    k_final<<<1, 256>>>(ftgt, out);                          // 9
}

// round 14
// speedup vs baseline: 1.1717x; 1.1717x over previous
#include <cuda_runtime.h>
#include <math.h>
#include <stdint.h>

#define N_PTS 65536
#define DIMS  64
#define KCL   128
#define ABLK  128
#define NBLK  (N_PTS / ABLK)      // 512
#define KD    (KCL * DIMS)        // 8192
#define EPSV  1e-8f
#define BIGF  3.402823466e38f
#define RT    512                 // radixL threads
#define NW    (RT / 32)           // 16 warps
#define HALF  16384
#define MT    512                 // merge threads
#define SKW(i) ((i) + ((i) >> 5)) // bank-skewed shared index
#define MBUF  (8192 + 256)        // skewed buffer size (floats)

__device__ int    g_pred[N_PTS];
__device__ int    g_histx[NBLK * KCL];
__device__ int    g_histt[NBLK * KCL];
__device__ float  g_fillp[NBLK * KCL];
__device__ float  g_fill[KCL];
__device__ int    g_m[KCL];
__device__ int    g_P[KCL];
__device__ int    g_off[KCL];
__device__ float  g_part[KD];
__device__ int    g_l1a[KCL], g_l1b[KCL], g_l2a[KCL], g_l2b[KCL], g_l3[KCL];
__device__ int    g_n1a, g_n1b, g_n2a, g_n2b, g_n3;
__device__ float  g_xg[(size_t)(2 * N_PTS) * DIMS];
__device__ float  g_tg[(size_t)(2 * N_PTS) * DIMS];

// ----------------------------------------------------------------------------
// K1: distances, argmin, soft filling, per-block histograms.
// ----------------------------------------------------------------------------
__global__ void k_assign(const float* __restrict__ x, const float* __restrict__ cc,
                         const int* __restrict__ predt) {
    extern __shared__ float dyn[];
    float* sc    = dyn;
    float* scn   = sc + KCL * DIMS;
    float* wca   = scn + KCL;
    float* sfill = wca + KCL * ABLK;
    int*   shx   = (int*)(sfill + KCL);
    int*   sht   = shx + KCL;

    const int tid = threadIdx.x;

    for (int j = tid; j < KCL * DIMS; j += ABLK) sc[j] = cc[j];
    if (tid < KCL) { sfill[tid] = 0.0f; shx[tid] = 0; sht[tid] = 0; }
    __syncthreads();
    if (tid < KCL) {
        float s = 0.0f;
        const float* cp = sc + tid * DIMS;
        #pragma unroll
        for (int d = 0; d < DIMS; d++) s += cp[d] * cp[d];
        scn[tid] = s;
    }
    __syncthreads();

    const int i = blockIdx.x * ABLK + tid;
    float xr[DIMS];
    {
        const float4* xp = (const float4*)(x + (size_t)i * DIMS);
        #pragma unroll
        for (int q = 0; q < 16; q++) {
            float4 v = xp[q];
            xr[4*q] = v.x; xr[4*q+1] = v.y; xr[4*q+2] = v.z; xr[4*q+3] = v.w;
        }
    }
    float xn = 0.0f;
    #pragma unroll
    for (int d = 0; d < DIMS; d++) xn += xr[d] * xr[d];

    float wsum = 0.0f, best = BIGF;
    int bc = 0;
    for (int c = 0; c < KCL; c++) {
        const float4* cp = (const float4*)(sc + c * DIMS);
        float a0 = 0.f, a1 = 0.f, a2 = 0.f, a3 = 0.f;
        #pragma unroll
        for (int q = 0; q < 16; q++) {
            float4 v = cp[q];
            a0 += xr[4*q]   * v.x;
            a1 += xr[4*q+1] * v.y;
            a2 += xr[4*q+2] * v.z;
            a3 += xr[4*q+3] * v.w;
        }
        float dot = (a0 + a1) + (a2 + a3);
        float d2 = xn + scn[c] - 2.0f * dot;
        float dist = sqrtf(fmaxf(d2, 0.0f));
        if (dist < best) { best = dist; bc = c; }
        float w = __fdividef(1.0f, dist + EPSV);
        wca[c * ABLK + tid] = w;
        wsum += w;
    }
    const float inv = __fdividef(1.0f, wsum);
    const int lane = tid & 31;

    for (int c = 0; c < KCL; c++) {
        float w = wca[c * ABLK + tid] * inv;
        #pragma unroll
        for (int o = 16; o > 0; o >>= 1) w += __shfl_down_sync(0xffffffffu, w, o);
        if (lane == 0) atomicAdd(&sfill[c], w);
    }

    g_pred[i] = bc;
    atomicAdd(&shx[bc], 1);
    atomicAdd(&sht[predt[i]], 1);
    __syncthreads();
    if (tid < KCL) {
        g_fillp[blockIdx.x * KCL + tid] = sfill[tid];
        g_histx[blockIdx.x * KCL + tid] = shx[tid];
        g_histt[blockIdx.x * KCL + tid] = sht[tid];
    }
}

// ----------------------------------------------------------------------------
// K2: per-cluster scan of block hists + m, P + fill reduction.
// ----------------------------------------------------------------------------
__global__ void k_scan1() {
    const int c = blockIdx.x;
    const int t = threadIdx.x;
    __shared__ int   s[NBLK];
    __shared__ float sf[NBLK];

    int v = g_histx[t * KCL + c];
    s[t] = v; __syncthreads();
    int acc = v;
    for (int o = 1; o < NBLK; o <<= 1) {
        int add = (t >= o) ? s[t - o] : 0;
        __syncthreads();
        acc += add; s[t] = acc;
        __syncthreads();
    }
    g_histx[t * KCL + c] = acc - v;
    int cntx = s[NBLK - 1];
    __syncthreads();

    v = g_histt[t * KCL + c];
    s[t] = v; __syncthreads();
    acc = v;
    for (int o = 1; o < NBLK; o <<= 1) {
        int add = (t >= o) ? s[t - o] : 0;
        __syncthreads();
        acc += add; s[t] = acc;
        __syncthreads();
    }
    g_histt[t * KCL + c] = acc - v;
    int cntt = s[NBLK - 1];
    __syncthreads();

    sf[t] = g_fillp[t * KCL + c];
    __syncthreads();
    for (int o = NBLK / 2; o > 0; o >>= 1) {
        if (t < o) sf[t] += sf[t + o];
        __syncthreads();
    }

    if (t == 0) {
        g_fill[c] = sf[0];
        int m = min(cntx, cntt);
        g_m[c] = m;
        int P = 0;
        if (m > 0) { P = 1; while (P < m) P <<= 1; }
        g_P[c] = P;
    }
}

// ----------------------------------------------------------------------------
// K3: stable rank + gather both sides; builds g_off and tier work lists.
// Lists: l1a = P<=512, l1b = P==1024, l2a = 2048..8192, l2b = 16K/32K, l3 = rest
// ----------------------------------------------------------------------------
__global__ void k_scatter2(const float* __restrict__ x, const float* __restrict__ tgt,
                           const int* __restrict__ predt) {
    __shared__ int cntx[KCL];
    __shared__ int cntt[KCL];
    __shared__ int soff[KCL];
    __shared__ int f1a[KCL], f1b[KCL], f2a[KCL], f2b[KCL], f3[KCL];
    const int tid = threadIdx.x;   // blockDim = 128 = KCL
    cntx[tid] = 0; cntt[tid] = 0;

    const int mC = g_m[tid];
    const int PC = g_P[tid];
    soff[tid] = PC;
    f1a[tid] = (mC >= 2 && PC <= 512) ? 1 : 0;
    f1b[tid] = (PC == 1024) ? 1 : 0;
    f2a[tid] = (PC >= 2048 && PC <= 8192) ? 1 : 0;
    f2b[tid] = (PC == 16384 || PC == 32768) ? 1 : 0;
    f3[tid]  = (PC > 32768) ? 1 : 0;
    __syncthreads();

    int aoff = soff[tid], a1a = f1a[tid], a1b = f1b[tid],
        a2a = f2a[tid], a2b = f2b[tid], a3 = f3[tid];
    for (int o = 1; o < KCL; o <<= 1) {
        int b0 = (tid >= o) ? soff[tid - o] : 0;
        int b1 = (tid >= o) ? f1a[tid - o] : 0;
        int b2 = (tid >= o) ? f1b[tid - o] : 0;
        int b3 = (tid >= o) ? f2a[tid - o] : 0;
        int b4 = (tid >= o) ? f2b[tid - o] : 0;
        int b5 = (tid >= o) ? f3[tid - o]  : 0;
        __syncthreads();
        aoff += b0; a1a += b1; a1b += b2; a2a += b3; a2b += b4; a3 += b5;
        soff[tid] = aoff; f1a[tid] = a1a; f1b[tid] = a1b;
        f2a[tid] = a2a; f2b[tid] = a2b; f3[tid] = a3;
        __syncthreads();
    }
    soff[tid] = aoff - PC;
    g_off[tid] = soff[tid];
    if (mC >= 2 && PC <= 512)            g_l1a[a1a - 1] = tid;
    if (PC == 1024)                      g_l1b[a1b - 1] = tid;
    if (PC >= 2048 && PC <= 8192)        g_l2a[a2a - 1] = tid;
    if (PC == 16384 || PC == 32768)      g_l2b[a2b - 1] = tid;
    if (PC > 32768)                      g_l3[a3 - 1]  = tid;
    if (tid == KCL - 1) {
        g_n1a = a1a; g_n1b = a1b; g_n2a = a2a; g_n2b = a2b; g_n3 = a3;
    }
    __syncthreads();

    const int i = blockIdx.x * ABLK + tid;
    const int cx = g_pred[i];
    const int ct = predt[i];
    const int myw = tid >> 5, lane = tid & 31;
    int rx = 0, rt = 0;

    for (int w = 0; w < ABLK / 32; w++) {
        if (myw == w) {
            unsigned peers = __match_any_sync(0xffffffffu, cx);
            unsigned lower = peers & ((1u << lane) - 1u);
            int leader = __ffs(peers) - 1;
            int base = 0;
            if (lane == leader) base = atomicAdd(&cntx[cx], __popc(peers));
            base = __shfl_sync(0xffffffffu, base, leader);
            rx = base + __popc(lower);

            peers = __match_any_sync(0xffffffffu, ct);
            lower = peers & ((1u << lane) - 1u);
            leader = __ffs(peers) - 1;
            base = 0;
            if (lane == leader) base = atomicAdd(&cntt[ct], __popc(peers));
            base = __shfl_sync(0xffffffffu, base, leader);
            rt = base + __popc(lower);
        }
        __syncthreads();
    }

    {
        const int r = g_histx[blockIdx.x * KCL + cx] + rx;
        if (r < g_m[cx]) {
            const int P = g_P[cx];
            float* dst = g_xg + (size_t)soff[cx] * DIMS + r;
            const float4* sp = (const float4*)(x + (size_t)i * DIMS);
            #pragma unroll
            for (int q = 0; q < 16; q++) {
                float4 v = sp[q];
                dst[(size_t)(4*q)     * P] = v.x;
                dst[(size_t)(4*q + 1) * P] = v.y;
                dst[(size_t)(4*q + 2) * P] = v.z;
                dst[(size_t)(4*q + 3) * P] = v.w;
            }
        }
    }
    {
        const int r = g_histt[blockIdx.x * KCL + ct] + rt;
        if (r < g_m[ct]) {
            const int P = g_P[ct];
            float* dst = g_tg + (size_t)soff[ct] * DIMS + r;
            const float4* sp = (const float4*)(tgt + (size_t)i * DIMS);
            #pragma unroll
            for (int q = 0; q < 16; q++) {
                float4 v = sp[q];
                dst[(size_t)(4*q)     * P] = v.x;
                dst[(size_t)(4*q + 1) * P] = v.y;
                dst[(size_t)(4*q + 2) * P] = v.z;
                dst[(size_t)(4*q + 3) * P] = v.w;
            }
        }
    }
}

// ----------------------------------------------------------------------------
// Warp-level in-register bitonic sort, fully unrolled templates.
// ----------------------------------------------------------------------------
template<int R, int JR>
__device__ __forceinline__ void reg_exch(float* v, int k) {
    #pragma unroll
    for (int r = 0; r < R; r++) {
        if ((r & JR) == 0) {
            float a = v[r], b = v[r | JR];
            bool up = (((r << 5) & k) == 0);
            float mn = fminf(a, b), mx = fmaxf(a, b);
            v[r]      = up ? mn : mx;
            v[r | JR] = up ? mx : mn;
        }
    }
}

template<int NE>
__device__ __forceinline__ void warp_sort_reg(float* v, int lane) {
    constexpr int R = NE / 32;
    #pragma unroll
    for (int k = 2; k <= NE; k <<= 1) {
        #pragma unroll
        for (int j = k >> 1; j >= 32; j >>= 1) {
            const int jr = j >> 5;
            if (jr == 1) reg_exch<R, 1>(v, k);
            if constexpr (R >= 4)  { if (jr == 2)  reg_exch<R, (R >= 4 ? 2 : 1)>(v, k); }
            if constexpr (R >= 8)  { if (jr == 4)  reg_exch<R, (R >= 8 ? 4 : 1)>(v, k); }
            if constexpr (R >= 16) { if (jr == 8)  reg_exch<R, (R >= 16 ? 8 : 1)>(v, k); }
            if constexpr (R >= 32) { if (jr == 16) reg_exch<R, (R >= 32 ? 16 : 1)>(v, k); }
        }
        const int j0 = (k >> 1 < 32) ? (k >> 1) : 16;
        #pragma unroll
        for (int j = j0; j >= 1; j >>= 1) {
            #pragma unroll
            for (int r = 0; r < R; r++) {
                int e = (r << 5) | lane;
                float pv = __shfl_xor_sync(0xffffffffu, v[r], j);
                bool desc  = (e & k) != 0;
                bool upper = (lane & j) != 0;
                v[r] = (upper != desc) ? fmaxf(v[r], pv) : fminf(v[r], pv);
            }
        }
    }
}

template<int NE>
__device__ __forceinline__ void warp_sort_seg(float* seg, int m, int lane) {
    constexpr int R = NE / 32;
    float v[R];
    #pragma unroll
    for (int q = 0; q < R; q++) {
        int e = q * 32 + lane;
        v[q] = (e < m) ? seg[e] : BIGF;
    }
    warp_sort_reg<NE>(v, lane);
    #pragma unroll
    for (int q = 0; q < R; q++) {
        int e = q * 32 + lane;
        if (e < m) seg[e] = v[q];
    }
}

// Warp-per-segment: P <= 512 (dedicated l1a list, no skipping).
__global__ void __launch_bounds__(256)
k_sort_warpA() {
    const int lane = threadIdx.x & 31;
    const int gw = (blockIdx.x * 256 + threadIdx.x) >> 5;
    const int nwarps = (gridDim.x * 256) >> 5;
    const int nseg = g_n1a * 128;

    for (int s = gw; s < nseg; s += nwarps) {
        const int c = g_l1a[s >> 7];
        const int P = g_P[c];
        const int r = s & 127;
        const int d = r & 63;
        const int m = g_m[c];
        float* seg = ((r >> 6) ? g_tg : g_xg) + (size_t)g_off[c] * DIMS + (size_t)d * P;

        if (P <= 64)        warp_sort_seg<64>(seg, m, lane);
        else if (P == 128)  warp_sort_seg<128>(seg, m, lane);
        else if (P == 256)  warp_sort_seg<256>(seg, m, lane);
        else                warp_sort_seg<512>(seg, m, lane);
    }
}

// Warp-per-segment: P == 1024 (dedicated l1b list).
__global__ void __launch_bounds__(256)
k_sort_warpB() {
    const int lane = threadIdx.x & 31;
    const int gw = (blockIdx.x * 256 + threadIdx.x) >> 5;
    const int nwarps = (gridDim.x * 256) >> 5;
    const int nseg = g_n1b * 128;

    for (int s = gw; s < nseg; s += nwarps) {
        const int c = g_l1b[s >> 7];
        const int r = s & 127;
        const int d = r & 63;
        const int m = g_m[c];
        float* seg = ((r >> 6) ? g_tg : g_xg) + (size_t)g_off[c] * DIMS + (size_t)d * 1024;
        warp_sort_seg<1024>(seg, m, lane);
    }
}

// ----------------------------------------------------------------------------
// Merge sort for P in {2048, 4096, 8192}: warp-register 512-run sorts + skewed
// (bank-conflict-free) merge-path rounds in shared.  (R12 proven form)
// ----------------------------------------------------------------------------
__global__ void __launch_bounds__(MT)
k_sort_merge() {
    extern __shared__ float sf2[];
    float* bufA = sf2;
    float* bufB = sf2 + MBUF;
    const int tid = threadIdx.x;
    const int w = tid >> 5, lane = tid & 31;
    const int nseg = g_n2a * 128;

    for (int s = blockIdx.x; s < nseg; s += gridDim.x) {
        const int c = g_l2a[s >> 7];
        const int r = s & 127;
        const int d = r & 63;
        const int m = g_m[c], P = g_P[c];
        float* seg = ((r >> 6) ? g_tg : g_xg) + (size_t)g_off[c] * DIMS + (size_t)d * P;

        for (int i = tid; i < P; i += MT)
            bufA[SKW(i)] = (i < m) ? seg[i] : BIGF;
        __syncthreads();

        // phase 1: warp-register sort of 512-element runs (ascending)
        const int nruns = P >> 9;
        for (int run = w; run < nruns; run += MT / 32) {
            const int rb = run * 512;
            float v[16];
            #pragma unroll
            for (int q = 0; q < 16; q++) v[q] = bufA[SKW(rb + q * 32 + lane)];
            warp_sort_reg<512>(v, lane);
            #pragma unroll
            for (int q = 0; q < 16; q++) bufA[SKW(rb + q * 32 + lane)] = v[q];
        }
        __syncthreads();

        // phase 2: merge-path rounds (skewed addressing, conflict-free)
        float* src = bufA;
        float* dst = bufB;
        const int G = P >> 9;                 // outputs per thread (4/8/16)
        for (int L = 512; L < P; L <<= 1) {
            const int k0 = tid * G;
            const int base = k0 & ~(2 * L - 1);
            const int kl = k0 - base;
            const int aoff = base, boff = base + L;
            int lo = kl - L; if (lo < 0) lo = 0;
            int hi = kl < L ? kl : L;
            while (lo < hi) {
                int mid = (lo + hi) >> 1;
                if (src[SKW(aoff + mid)] <= src[SKW(boff + kl - mid - 1)]) lo = mid + 1;
                else hi = mid;
            }
            int a = lo, b = kl - lo;
            #pragma unroll 4
            for (int o = 0; o < G; o++) {
                float va = (a < L) ? src[SKW(aoff + a)] : BIGF;
                float vb = (b < L) ? src[SKW(boff + b)] : BIGF;
                if (va <= vb) { dst[SKW(k0 + o)] = va; a++; }
                else          { dst[SKW(k0 + o)] = vb; b++; }
            }
            __syncthreads();
            float* t = src; src = dst; dst = t;
        }

        for (int i = tid; i < m; i += MT) seg[i] = src[SKW(i)];
        __syncthreads();
    }
}

// ----------------------------------------------------------------------------
// Radix machinery (only for P in {16384, 32768}; measured near-empty)
// ----------------------------------------------------------------------------
__device__ __forceinline__ unsigned f2k(float f) {
    unsigned b = __float_as_uint(f);
    return (b & 0x80000000u) ? ~b : (b | 0x80000000u);
}
__device__ __forceinline__ float k2f(unsigned k) {
    unsigned b = (k & 0x80000000u) ? (k & 0x7FFFFFFFu) : ~k;
    return __uint_as_float(b);
}

__device__ void radix_pass(const unsigned* src, unsigned* dst, unsigned* hist,
                           unsigned* tot, int n, int shift) {
    const int tid = threadIdx.x, w = tid >> 5, l = tid & 31;
    const int E = n / RT;
    const int wbase = w * 32 * E;

    for (int i = tid; i < NW * 256; i += RT) hist[i] = 0;
    __syncthreads();

    for (int e = 0; e < E; e++) {
        unsigned u = src[wbase + e * 32 + l];
        atomicAdd(&hist[w * 256 + ((u >> shift) & 255u)], 1u);
    }
    __syncthreads();

    if (tid < 256) {
        unsigned run = 0;
        #pragma unroll
        for (int ww = 0; ww < NW; ww++) {
            unsigned t = hist[ww * 256 + tid];
            hist[ww * 256 + tid] = run;
            run += t;
        }
        tot[tid] = run;
    }
    __syncthreads();

    if (w == 0) {
        unsigned v[8], lsum = 0;
        #pragma unroll
        for (int q = 0; q < 8; q++) { v[q] = tot[l * 8 + q]; lsum += v[q]; }
        unsigned excl = lsum;
        #pragma unroll
        for (int o = 1; o < 32; o <<= 1) {
            unsigned t = __shfl_up_sync(0xffffffffu, excl, o);
            if (l >= o) excl += t;
        }
        excl -= lsum;
        #pragma unroll
        for (int q = 0; q < 8; q++) {
            unsigned t = v[q];
            tot[l * 8 + q] = excl;
            excl += t;
        }
    }
    __syncthreads();

    for (int i = tid; i < NW * 256; i += RT) hist[i] += tot[i & 255];
    __syncthreads();

    for (int e = 0; e < E; e++) {
        unsigned u = src[wbase + e * 32 + l];
        unsigned d = (u >> shift) & 255u;
        unsigned peers = __match_any_sync(0xffffffffu, d);
        int leader = __ffs(peers) - 1;
        unsigned base = 0;
        if (l == leader) base = hist[w * 256 + d];
        base = __shfl_sync(0xffffffffu, base, leader);
        unsigned rank = base + __popc(peers & ((1u << l) - 1u));
        if (l == leader) hist[w * 256 + d] = base + __popc(peers);
        dst[rank] = u;
    }
    __syncthreads();
}

__device__ void radix_sort_n(unsigned* A, unsigned* PP, unsigned* hist,
                             unsigned* tot, int n) {
    radix_pass(A, PP, hist, tot, n, 0);
    radix_pass(PP, A, hist, tot, n, 8);
    radix_pass(A, PP, hist, tot, n, 16);
    radix_pass(PP, A, hist, tot, n, 24);
}

__device__ void merge_write(const unsigned* A, const unsigned* B, float* out) {
    const int tid = threadIdx.x;
    const int k0 = tid * (2 * HALF / RT);
    int lo = max(0, k0 - HALF), hi = min(k0, HALF);
    while (lo < hi) {
        int mid = (lo + hi) >> 1;
        if (A[mid] <= B[k0 - mid - 1]) lo = mid + 1; else hi = mid;
    }
    int a = lo, b = k0 - lo;
    #pragma unroll 4
    for (int o = 0; o < 2 * HALF / RT; o++) {
        unsigned va = (a < HALF) ? A[a] : 0xFFFFFFFFu;
        unsigned vb = (b < HALF) ? B[b] : 0xFFFFFFFFu;
        unsigned v;
        if (va <= vb) { v = va; a++; } else { v = vb; b++; }
        out[k0 + o] = k2f(v);
    }
}

__global__ void __launch_bounds__(RT)
k_sort_radixL() {
    extern __shared__ unsigned su[];
    unsigned* R0 = su;
    unsigned* R1 = su + HALF;
    unsigned* R2 = su + 2 * HALF;
    unsigned* hist = su + 3 * HALF;
    unsigned* tot = hist + NW * 256;
    const int tid = threadIdx.x;
    const int nseg = g_n2b * 128;

    for (int s = blockIdx.x; s < nseg; s += gridDim.x) {
        const int c = g_l2b[s >> 7];
        const int r = s & 127;
        const int d = r & 63;
        const int m = g_m[c], P = g_P[c];
        float* seg = ((r >> 6) ? g_tg : g_xg) + (size_t)g_off[c] * DIMS + (size_t)d * P;

        if (m <= HALF) {
            const int n = ((m + RT - 1) / RT) * RT;
            for (int i = tid; i < n; i += RT)
                R0[i] = (i < m) ? f2k(seg[i]) : 0xFFFFFFFFu;
            __syncthreads();
            radix_sort_n(R0, R2, hist, tot, n);
            for (int i = tid; i < m; i += RT) seg[i] = k2f(R0[i]);
        } else {
            for (int i = tid; i < HALF; i += RT)
                R0[i] = (i < m) ? f2k(seg[i]) : 0xFFFFFFFFu;
            __syncthreads();
            radix_sort_n(R0, R2, hist, tot, HALF);
            for (int i = tid; i < HALF; i += RT) {
                int j = HALF + i;
                R1[i] = (j < m) ? f2k(seg[j]) : 0xFFFFFFFFu;
            }
            __syncthreads();
            radix_sort_n(R1, R2, hist, tot, HALF);
            merge_write(R0, R1, seg);
        }
        __syncthreads();
    }
}

// Global bitonic fallback, P > 32768 (safety; expected empty)
__global__ void __launch_bounds__(1024)
k_sort_t3() {
    const int T = blockDim.x, tid = threadIdx.x;
    const int nseg = g_n3 * 128;
    for (int s = blockIdx.x; s < nseg; s += gridDim.x) {
        const int c = g_l3[s >> 7];
        const int r = s & 127;
        const int d = r & 63;
        const int m = g_m[c], P = g_P[c];
        float* seg = ((r >> 6) ? g_tg : g_xg) + (size_t)g_off[c] * DIMS + (size_t)d * P;
        for (int j = m + tid; j < P; j += T) seg[j] = BIGF;
        __syncthreads();
        for (int k = 2; k <= P; k <<= 1) {
            for (int j = k >> 1; j > 0; j >>= 1) {
                for (int idx = tid; idx < P; idx += T) {
                    int l = idx ^ j;
                    if (l > idx) {
                        float a = seg[idx], b = seg[l];
                        bool up = ((idx & k) == 0);
                        if ((a > b) == up) { seg[idx] = b; seg[l] = a; }
                    }
                }
                __syncthreads();
            }
        }
        __syncthreads();
    }
}

// ----------------------------------------------------------------------------
// K5: Wasserstein partials per (cluster, dim)
// ----------------------------------------------------------------------------
__global__ void k_diff() {
    const int cd = blockIdx.x;
    const int c = cd >> 6, d = cd & 63;
    const int m = g_m[c];
    if (m < 1) { if (threadIdx.x == 0) g_part[cd] = 0.0f; return; }
    const int P = g_P[c];
    const size_t base = (size_t)g_off[c] * DIMS + (size_t)d * P;

    float s = 0.0f;
    for (int j = threadIdx.x; j < m; j += blockDim.x)
        s += fabsf(g_xg[base + j] - g_tg[base + j]);

    __shared__ float red[256];
    red[threadIdx.x] = s;
    __syncthreads();
    for (int o = blockDim.x >> 1; o > 0; o >>= 1) {
        if (threadIdx.x < o) red[threadIdx.x] += red[threadIdx.x + o];
        __syncthreads();
    }
    if (threadIdx.x == 0)
        g_part[cd] = red[0] / ((float)m * DIMS);
}

// ----------------------------------------------------------------------------
// K6: finalize
// ----------------------------------------------------------------------------
__global__ void k_final(const float* __restrict__ ftgt, float* out) {
    const int tid = threadIdx.x;
    __shared__ double red[256];

    double s = 0.0;
    for (int i = tid; i < KD; i += 256) s += (double)g_part[i];
    red[tid] = s;
    __syncthreads();
    for (int o = 128; o > 0; o >>= 1) {
        if (tid < o) red[tid] += red[tid + o];
        __syncthreads();
    }

    if (tid == 0) {
        float lf = 0.0f;
        for (int c = 0; c < KCL; c++) {
            float diff = g_fill[c] * (1.0f / N_PTS) - ftgt[c];
            lf += diff * diff;
        }
        out[0] = (float)((double)(lf / KCL) + red[0]);
    }
}

// ----------------------------------------------------------------------------
// Launch
// ----------------------------------------------------------------------------
extern "C" void kernel_launch(void* const* d_in, const int* in_sizes, int n_in,
                              void* d_out, int out_size) {
    const float* x     = (const float*)d_in[0];
    const float* tgt   = (const float*)d_in[1];
    const float* cc    = (const float*)d_in[2];
    const int*   predt = (const int*)d_in[3];
    const float* ftgt  = (const float*)d_in[4];
    float* out = (float*)d_out;

    const int ASSIGN_SMEM = (KCL * DIMS + KCL + KCL * ABLK + KCL) * 4 + KCL * 8;
    const int MERGE_SMEM = 2 * MBUF * 4;                     // 67584 B
    const int RADL_SMEM = (3 * HALF + NW * 256 + 256) * 4;   // 214016 B
    cudaFuncSetAttribute(k_assign,
                         cudaFuncAttributeMaxDynamicSharedMemorySize, ASSIGN_SMEM);
    cudaFuncSetAttribute(k_sort_merge,
                         cudaFuncAttributeMaxDynamicSharedMemorySize, MERGE_SMEM);
    cudaFuncSetAttribute(k_sort_radixL,
                         cudaFuncAttributeMaxDynamicSharedMemorySize, RADL_SMEM);

    k_assign<<<NBLK, ABLK, ASSIGN_SMEM>>>(x, cc, predt);     // 0
    k_scan1<<<KCL, NBLK>>>();                                // 1
    k_scatter2<<<NBLK, ABLK>>>(x, tgt, predt);               // 2
    k_sort_warpA<<<2048, 256>>>();                           // 3 <- ncu (measure warp tier)
    k_sort_warpB<<<1024, 256>>>();                           // 4
    k_sort_merge<<<444, MT, MERGE_SMEM>>>();                 // 5
    k_sort_radixL<<<148, RT, RADL_SMEM>>>();                 // 6
    k_sort_t3<<<148, 1024>>>();                              // 7
    k_diff<<<KD, 256>>>();                                   // 8
    k_final<<<1, 256>>>(ftgt, out);                          // 9
}

// round 15
// speedup vs baseline: 1.1975x; 1.0220x over previous
#include <cuda_runtime.h>
#include <math.h>
#include <stdint.h>

#define N_PTS 65536
#define DIMS  64
#define KCL   128
#define ABLK  128
#define NBLK  (N_PTS / ABLK)      // 512
#define KD    (KCL * DIMS)        // 8192
#define EPSV  1e-8f
#define BIGF  3.402823466e38f
#define RT    512                 // radixL threads
#define NW    (RT / 32)           // 16 warps
#define HALF  16384
#define MT    512                 // merge threads
#define SKW(i) ((i) + ((i) >> 5)) // bank-skewed shared index
#define MBUF  (8192 + 256)        // skewed buffer size (floats)

__device__ int    g_pred[N_PTS];
__device__ int    g_histx[NBLK * KCL];
__device__ int    g_histt[NBLK * KCL];
__device__ float  g_fillp[NBLK * KCL];
__device__ float  g_fill[KCL];
__device__ int    g_m[KCL];
__device__ int    g_P[KCL];
__device__ int    g_off[KCL];
__device__ float  g_part[KD];
__device__ int    g_l1a[KCL], g_l1b[KCL], g_l2a[KCL], g_l2b[KCL], g_l3[KCL];
__device__ int    g_n1a, g_n1b, g_n2a, g_n2b, g_n3;
__device__ float  g_xg[(size_t)(2 * N_PTS) * DIMS];
__device__ float  g_tg[(size_t)(2 * N_PTS) * DIMS];

// ----------------------------------------------------------------------------
// K1: distances, argmin, soft filling, per-block histograms.
// ----------------------------------------------------------------------------
__global__ void k_assign(const float* __restrict__ x, const float* __restrict__ cc,
                         const int* __restrict__ predt) {
    extern __shared__ float dyn[];
    float* sc    = dyn;
    float* scn   = sc + KCL * DIMS;
    float* wca   = scn + KCL;
    float* sfill = wca + KCL * ABLK;
    int*   shx   = (int*)(sfill + KCL);
    int*   sht   = shx + KCL;

    const int tid = threadIdx.x;

    for (int j = tid; j < KCL * DIMS; j += ABLK) sc[j] = cc[j];
    if (tid < KCL) { sfill[tid] = 0.0f; shx[tid] = 0; sht[tid] = 0; }
    __syncthreads();
    if (tid < KCL) {
        float s = 0.0f;
        const float* cp = sc + tid * DIMS;
        #pragma unroll
        for (int d = 0; d < DIMS; d++) s += cp[d] * cp[d];
        scn[tid] = s;
    }
    __syncthreads();

    const int i = blockIdx.x * ABLK + tid;
    float xr[DIMS];
    {
        const float4* xp = (const float4*)(x + (size_t)i * DIMS);
        #pragma unroll
        for (int q = 0; q < 16; q++) {
            float4 v = xp[q];
            xr[4*q] = v.x; xr[4*q+1] = v.y; xr[4*q+2] = v.z; xr[4*q+3] = v.w;
        }
    }
    float xn = 0.0f;
    #pragma unroll
    for (int d = 0; d < DIMS; d++) xn += xr[d] * xr[d];

    float wsum = 0.0f, best = BIGF;
    int bc = 0;
    for (int c = 0; c < KCL; c++) {
        const float4* cp = (const float4*)(sc + c * DIMS);
        float a0 = 0.f, a1 = 0.f, a2 = 0.f, a3 = 0.f;
        #pragma unroll
        for (int q = 0; q < 16; q++) {
            float4 v = cp[q];
            a0 += xr[4*q]   * v.x;
            a1 += xr[4*q+1] * v.y;
            a2 += xr[4*q+2] * v.z;
            a3 += xr[4*q+3] * v.w;
        }
        float dot = (a0 + a1) + (a2 + a3);
        float d2 = xn + scn[c] - 2.0f * dot;
        float dist = sqrtf(fmaxf(d2, 0.0f));
        if (dist < best) { best = dist; bc = c; }
        float w = __fdividef(1.0f, dist + EPSV);
        wca[c * ABLK + tid] = w;
        wsum += w;
    }
    const float inv = __fdividef(1.0f, wsum);
    const int lane = tid & 31;

    for (int c = 0; c < KCL; c++) {
        float w = wca[c * ABLK + tid] * inv;
        #pragma unroll
        for (int o = 16; o > 0; o >>= 1) w += __shfl_down_sync(0xffffffffu, w, o);
        if (lane == 0) atomicAdd(&sfill[c], w);
    }

    g_pred[i] = bc;
    atomicAdd(&shx[bc], 1);
    atomicAdd(&sht[predt[i]], 1);
    __syncthreads();
    if (tid < KCL) {
        g_fillp[blockIdx.x * KCL + tid] = sfill[tid];
        g_histx[blockIdx.x * KCL + tid] = shx[tid];
        g_histt[blockIdx.x * KCL + tid] = sht[tid];
    }
}

// ----------------------------------------------------------------------------
// K2: per-cluster scan of block hists + m, P + fill reduction.
// ----------------------------------------------------------------------------
__global__ void k_scan1() {
    const int c = blockIdx.x;
    const int t = threadIdx.x;
    __shared__ int   s[NBLK];
    __shared__ float sf[NBLK];

    int v = g_histx[t * KCL + c];
    s[t] = v; __syncthreads();
    int acc = v;
    for (int o = 1; o < NBLK; o <<= 1) {
        int add = (t >= o) ? s[t - o] : 0;
        __syncthreads();
        acc += add; s[t] = acc;
        __syncthreads();
    }
    g_histx[t * KCL + c] = acc - v;
    int cntx = s[NBLK - 1];
    __syncthreads();

    v = g_histt[t * KCL + c];
    s[t] = v; __syncthreads();
    acc = v;
    for (int o = 1; o < NBLK; o <<= 1) {
        int add = (t >= o) ? s[t - o] : 0;
        __syncthreads();
        acc += add; s[t] = acc;
        __syncthreads();
    }
    g_histt[t * KCL + c] = acc - v;
    int cntt = s[NBLK - 1];
    __syncthreads();

    sf[t] = g_fillp[t * KCL + c];
    __syncthreads();
    for (int o = NBLK / 2; o > 0; o >>= 1) {
        if (t < o) sf[t] += sf[t + o];
        __syncthreads();
    }

    if (t == 0) {
        g_fill[c] = sf[0];
        int m = min(cntx, cntt);
        g_m[c] = m;
        int P = 0;
        if (m > 0) { P = 1; while (P < m) P <<= 1; }
        g_P[c] = P;
    }
}

// ----------------------------------------------------------------------------
// K3: stable rank + gather both sides; builds g_off and tier work lists.
// ----------------------------------------------------------------------------
__global__ void k_scatter2(const float* __restrict__ x, const float* __restrict__ tgt,
                           const int* __restrict__ predt) {
    __shared__ int cntx[KCL];
    __shared__ int cntt[KCL];
    __shared__ int soff[KCL];
    __shared__ int f1a[KCL], f1b[KCL], f2a[KCL], f2b[KCL], f3[KCL];
    const int tid = threadIdx.x;   // blockDim = 128 = KCL
    cntx[tid] = 0; cntt[tid] = 0;

    const int mC = g_m[tid];
    const int PC = g_P[tid];
    soff[tid] = PC;
    f1a[tid] = (mC >= 2 && PC <= 512) ? 1 : 0;
    f1b[tid] = (PC == 1024) ? 1 : 0;
    f2a[tid] = (PC >= 2048 && PC <= 8192) ? 1 : 0;
    f2b[tid] = (PC == 16384 || PC == 32768) ? 1 : 0;
    f3[tid]  = (PC > 32768) ? 1 : 0;
    __syncthreads();

    int aoff = soff[tid], a1a = f1a[tid], a1b = f1b[tid],
        a2a = f2a[tid], a2b = f2b[tid], a3 = f3[tid];
    for (int o = 1; o < KCL; o <<= 1) {
        int b0 = (tid >= o) ? soff[tid - o] : 0;
        int b1 = (tid >= o) ? f1a[tid - o] : 0;
        int b2 = (tid >= o) ? f1b[tid - o] : 0;
        int b3 = (tid >= o) ? f2a[tid - o] : 0;
        int b4 = (tid >= o) ? f2b[tid - o] : 0;
        int b5 = (tid >= o) ? f3[tid - o]  : 0;
        __syncthreads();
        aoff += b0; a1a += b1; a1b += b2; a2a += b3; a2b += b4; a3 += b5;
        soff[tid] = aoff; f1a[tid] = a1a; f1b[tid] = a1b;
        f2a[tid] = a2a; f2b[tid] = a2b; f3[tid] = a3;
        __syncthreads();
    }
    soff[tid] = aoff - PC;
    g_off[tid] = soff[tid];
    if (mC >= 2 && PC <= 512)            g_l1a[a1a - 1] = tid;
    if (PC == 1024)                      g_l1b[a1b - 1] = tid;
    if (PC >= 2048 && PC <= 8192)        g_l2a[a2a - 1] = tid;
    if (PC == 16384 || PC == 32768)      g_l2b[a2b - 1] = tid;
    if (PC > 32768)                      g_l3[a3 - 1]  = tid;
    if (tid == KCL - 1) {
        g_n1a = a1a; g_n1b = a1b; g_n2a = a2a; g_n2b = a2b; g_n3 = a3;
    }
    __syncthreads();

    const int i = blockIdx.x * ABLK + tid;
    const int cx = g_pred[i];
    const int ct = predt[i];
    const int myw = tid >> 5, lane = tid & 31;
    int rx = 0, rt = 0;

    for (int w = 0; w < ABLK / 32; w++) {
        if (myw == w) {
            unsigned peers = __match_any_sync(0xffffffffu, cx);
            unsigned lower = peers & ((1u << lane) - 1u);
            int leader = __ffs(peers) - 1;
            int base = 0;
            if (lane == leader) base = atomicAdd(&cntx[cx], __popc(peers));
            base = __shfl_sync(0xffffffffu, base, leader);
            rx = base + __popc(lower);

            peers = __match_any_sync(0xffffffffu, ct);
            lower = peers & ((1u << lane) - 1u);
            leader = __ffs(peers) - 1;
            base = 0;
            if (lane == leader) base = atomicAdd(&cntt[ct], __popc(peers));
            base = __shfl_sync(0xffffffffu, base, leader);
            rt = base + __popc(lower);
        }
        __syncthreads();
    }

    {
        const int r = g_histx[blockIdx.x * KCL + cx] + rx;
        if (r < g_m[cx]) {
            const int P = g_P[cx];
            float* dst = g_xg + (size_t)soff[cx] * DIMS + r;
            const float4* sp = (const float4*)(x + (size_t)i * DIMS);
            #pragma unroll
            for (int q = 0; q < 16; q++) {
                float4 v = sp[q];
                dst[(size_t)(4*q)     * P] = v.x;
                dst[(size_t)(4*q + 1) * P] = v.y;
                dst[(size_t)(4*q + 2) * P] = v.z;
                dst[(size_t)(4*q + 3) * P] = v.w;
            }
        }
    }
    {
        const int r = g_histt[blockIdx.x * KCL + ct] + rt;
        if (r < g_m[ct]) {
            const int P = g_P[ct];
            float* dst = g_tg + (size_t)soff[ct] * DIMS + r;
            const float4* sp = (const float4*)(tgt + (size_t)i * DIMS);
            #pragma unroll
            for (int q = 0; q < 16; q++) {
                float4 v = sp[q];
                dst[(size_t)(4*q)     * P] = v.x;
                dst[(size_t)(4*q + 1) * P] = v.y;
                dst[(size_t)(4*q + 2) * P] = v.z;
                dst[(size_t)(4*q + 3) * P] = v.w;
            }
        }
    }
}

// ----------------------------------------------------------------------------
// Warp-level in-register bitonic sort, fully unrolled templates.
// ----------------------------------------------------------------------------
template<int R, int JR>
__device__ __forceinline__ void reg_exch(float* v, int k) {
    #pragma unroll
    for (int r = 0; r < R; r++) {
        if ((r & JR) == 0) {
            float a = v[r], b = v[r | JR];
            bool up = (((r << 5) & k) == 0);
            float mn = fminf(a, b), mx = fmaxf(a, b);
            v[r]      = up ? mn : mx;
            v[r | JR] = up ? mx : mn;
        }
    }
}

template<int NE>
__device__ __forceinline__ void warp_sort_reg(float* v, int lane) {
    constexpr int R = NE / 32;
    #pragma unroll
    for (int k = 2; k <= NE; k <<= 1) {
        #pragma unroll
        for (int j = k >> 1; j >= 32; j >>= 1) {
            const int jr = j >> 5;
            if (jr == 1) reg_exch<R, 1>(v, k);
            if constexpr (R >= 4)  { if (jr == 2)  reg_exch<R, (R >= 4 ? 2 : 1)>(v, k); }
            if constexpr (R >= 8)  { if (jr == 4)  reg_exch<R, (R >= 8 ? 4 : 1)>(v, k); }
            if constexpr (R >= 16) { if (jr == 8)  reg_exch<R, (R >= 16 ? 8 : 1)>(v, k); }
            if constexpr (R >= 32) { if (jr == 16) reg_exch<R, (R >= 32 ? 16 : 1)>(v, k); }
        }
        const int j0 = (k >> 1 < 32) ? (k >> 1) : 16;
        #pragma unroll
        for (int j = j0; j >= 1; j >>= 1) {
            #pragma unroll
            for (int r = 0; r < R; r++) {
                int e = (r << 5) | lane;
                float pv = __shfl_xor_sync(0xffffffffu, v[r], j);
                bool desc  = (e & k) != 0;
                bool upper = (lane & j) != 0;
                v[r] = (upper != desc) ? fmaxf(v[r], pv) : fminf(v[r], pv);
            }
        }
    }
}

template<int NE>
__device__ __forceinline__ void warp_sort_seg(float* seg, int m, int lane) {
    constexpr int R = NE / 32;
    float v[R];
    #pragma unroll
    for (int q = 0; q < R; q++) {
        int e = q * 32 + lane;
        v[q] = (e < m) ? seg[e] : BIGF;
    }
    warp_sort_reg<NE>(v, lane);
    #pragma unroll
    for (int q = 0; q < R; q++) {
        int e = q * 32 + lane;
        if (e < m) seg[e] = v[q];
    }
}

// Warp-per-segment: P <= 512 (dedicated l1a list).
__global__ void __launch_bounds__(256)
k_sort_warpA() {
    const int lane = threadIdx.x & 31;
    const int gw = (blockIdx.x * 256 + threadIdx.x) >> 5;
    const int nwarps = (gridDim.x * 256) >> 5;
    const int nseg = g_n1a * 128;

    for (int s = gw; s < nseg; s += nwarps) {
        const int c = g_l1a[s >> 7];
        const int P = g_P[c];
        const int r = s & 127;
        const int d = r & 63;
        const int m = g_m[c];
        float* seg = ((r >> 6) ? g_tg : g_xg) + (size_t)g_off[c] * DIMS + (size_t)d * P;

        if (P <= 64)        warp_sort_seg<64>(seg, m, lane);
        else if (P == 128)  warp_sort_seg<128>(seg, m, lane);
        else if (P == 256)  warp_sort_seg<256>(seg, m, lane);
        else                warp_sort_seg<512>(seg, m, lane);
    }
}

// Warp-per-segment: P == 1024 (dedicated l1b list).
__global__ void __launch_bounds__(256)
k_sort_warpB() {
    const int lane = threadIdx.x & 31;
    const int gw = (blockIdx.x * 256 + threadIdx.x) >> 5;
    const int nwarps = (gridDim.x * 256) >> 5;
    const int nseg = g_n1b * 128;

    for (int s = gw; s < nseg; s += nwarps) {
        const int c = g_l1b[s >> 7];
        const int r = s & 127;
        const int d = r & 63;
        const int m = g_m[c];
        float* seg = ((r >> 6) ? g_tg : g_xg) + (size_t)g_off[c] * DIMS + (size_t)d * 1024;
        warp_sort_seg<1024>(seg, m, lane);
    }
}

// ----------------------------------------------------------------------------
// Merge sort for P in {2048, 4096, 8192}: phase-1 sorts 512-runs straight from
// GLOBAL into registers (coalesced), stores to skewed shared; merge-path rounds
// in shared; FINAL round (L=P/2) writes straight to global with <m guard.
// Removes the separate load and copy passes.
// ----------------------------------------------------------------------------
__global__ void __launch_bounds__(MT)
k_sort_merge() {
    extern __shared__ float sf2[];
    float* bufA = sf2;
    float* bufB = sf2 + MBUF;
    const int tid = threadIdx.x;
    const int w = tid >> 5, lane = tid & 31;
    const int nseg = g_n2a * 128;

    for (int s = blockIdx.x; s < nseg; s += gridDim.x) {
        const int c = g_l2a[s >> 7];
        const int r = s & 127;
        const int d = r & 63;
        const int m = g_m[c], P = g_P[c];
        float* seg = ((r >> 6) ? g_tg : g_xg) + (size_t)g_off[c] * DIMS + (size_t)d * P;

        // phase 1: warp-register sort of 512-runs loaded straight from global
        const int nruns = P >> 9;
        for (int run = w; run < nruns; run += MT / 32) {
            const int rb = run * 512;
            float v[16];
            #pragma unroll
            for (int q = 0; q < 16; q++) {
                int e = rb + q * 32 + lane;
                v[q] = (e < m) ? seg[e] : BIGF;
            }
            warp_sort_reg<512>(v, lane);
            #pragma unroll
            for (int q = 0; q < 16; q++)
                bufA[SKW(rb + q * 32 + lane)] = v[q];
        }
        __syncthreads();

        // phase 2a: merge-path rounds in shared while 2L < P
        float* src = bufA;
        float* dst = bufB;
        const int G = P >> 9;                 // outputs per thread (4/8/16)
        for (int L = 512; 2 * L < P; L <<= 1) {
            const int k0 = tid * G;
            const int base = k0 & ~(2 * L - 1);
            const int kl = k0 - base;
            const int aoff = base, boff = base + L;
            int lo = kl - L; if (lo < 0) lo = 0;
            int hi = kl < L ? kl : L;
            while (lo < hi) {
                int mid = (lo + hi) >> 1;
                if (src[SKW(aoff + mid)] <= src[SKW(boff + kl - mid - 1)]) lo = mid + 1;
                else hi = mid;
            }
            int a = lo, b = kl - lo;
            #pragma unroll 4
            for (int o = 0; o < G; o++) {
                float va = (a < L) ? src[SKW(aoff + a)] : BIGF;
                float vb = (b < L) ? src[SKW(boff + b)] : BIGF;
                if (va <= vb) { dst[SKW(k0 + o)] = va; a++; }
                else          { dst[SKW(k0 + o)] = vb; b++; }
            }
            __syncthreads();
            float* t = src; src = dst; dst = t;
        }

        // phase 2b: final round (L = P/2) writes straight to global, <m guard
        {
            const int L = P >> 1;
            const int k0 = tid * G;           // base == 0 for the single pair
            int lo = k0 - L; if (lo < 0) lo = 0;
            int hi = k0 < L ? k0 : L;
            while (lo < hi) {
                int mid = (lo + hi) >> 1;
                if (src[SKW(mid)] <= src[SKW(L + k0 - mid - 1)]) lo = mid + 1;
                else hi = mid;
            }
            int a = lo, b = k0 - lo;
            #pragma unroll 4
            for (int o = 0; o < G; o++) {
                float va = (a < L) ? src[SKW(a)] : BIGF;
                float vb = (b < L) ? src[SKW(L + b)] : BIGF;
                float vv;
                if (va <= vb) { vv = va; a++; } else { vv = vb; b++; }
                if (k0 + o < m) seg[k0 + o] = vv;
            }
        }
        __syncthreads();
    }
}

// ----------------------------------------------------------------------------
// Radix machinery (only for P in {16384, 32768}; measured near-empty)
// ----------------------------------------------------------------------------
__device__ __forceinline__ unsigned f2k(float f) {
    unsigned b = __float_as_uint(f);
    return (b & 0x80000000u) ? ~b : (b | 0x80000000u);
}
__device__ __forceinline__ float k2f(unsigned k) {
    unsigned b = (k & 0x80000000u) ? (k & 0x7FFFFFFFu) : ~k;
    return __uint_as_float(b);
}

__device__ void radix_pass(const unsigned* src, unsigned* dst, unsigned* hist,
                           unsigned* tot, int n, int shift) {
    const int tid = threadIdx.x, w = tid >> 5, l = tid & 31;
    const int E = n / RT;
    const int wbase = w * 32 * E;

    for (int i = tid; i < NW * 256; i += RT) hist[i] = 0;
    __syncthreads();

    for (int e = 0; e < E; e++) {
        unsigned u = src[wbase + e * 32 + l];
        atomicAdd(&hist[w * 256 + ((u >> shift) & 255u)], 1u);
    }
    __syncthreads();

    if (tid < 256) {
        unsigned run = 0;
        #pragma unroll
        for (int ww = 0; ww < NW; ww++) {
            unsigned t = hist[ww * 256 + tid];
            hist[ww * 256 + tid] = run;
            run += t;
        }
        tot[tid] = run;
    }
    __syncthreads();

    if (w == 0) {
        unsigned v[8], lsum = 0;
        #pragma unroll
        for (int q = 0; q < 8; q++) { v[q] = tot[l * 8 + q]; lsum += v[q]; }
        unsigned excl = lsum;
        #pragma unroll
        for (int o = 1; o < 32; o <<= 1) {
            unsigned t = __shfl_up_sync(0xffffffffu, excl, o);
            if (l >= o) excl += t;
        }
        excl -= lsum;
        #pragma unroll
        for (int q = 0; q < 8; q++) {
            unsigned t = v[q];
            tot[l * 8 + q] = excl;
            excl += t;
        }
    }
    __syncthreads();

    for (int i = tid; i < NW * 256; i += RT) hist[i] += tot[i & 255];
    __syncthreads();

    for (int e = 0; e < E; e++) {
        unsigned u = src[wbase + e * 32 + l];
        unsigned d = (u >> shift) & 255u;
        unsigned peers = __match_any_sync(0xffffffffu, d);
        int leader = __ffs(peers) - 1;
        unsigned base = 0;
        if (l == leader) base = hist[w * 256 + d];
        base = __shfl_sync(0xffffffffu, base, leader);
        unsigned rank = base + __popc(peers & ((1u << l) - 1u));
        if (l == leader) hist[w * 256 + d] = base + __popc(peers);
        dst[rank] = u;
    }
    __syncthreads();
}

__device__ void radix_sort_n(unsigned* A, unsigned* PP, unsigned* hist,
                             unsigned* tot, int n) {
    radix_pass(A, PP, hist, tot, n, 0);
    radix_pass(PP, A, hist, tot, n, 8);
    radix_pass(A, PP, hist, tot, n, 16);
    radix_pass(PP, A, hist, tot, n, 24);
}

__device__ void merge_write(const unsigned* A, const unsigned* B, float* out) {
    const int tid = threadIdx.x;
    const int k0 = tid * (2 * HALF / RT);
    int lo = max(0, k0 - HALF), hi = min(k0, HALF);
    while (lo < hi) {
        int mid = (lo + hi) >> 1;
        if (A[mid] <= B[k0 - mid - 1]) lo = mid + 1; else hi = mid;
    }
    int a = lo, b = k0 - lo;
    #pragma unroll 4
    for (int o = 0; o < 2 * HALF / RT; o++) {
        unsigned va = (a < HALF) ? A[a] : 0xFFFFFFFFu;
        unsigned vb = (b < HALF) ? B[b] : 0xFFFFFFFFu;
        unsigned v;
        if (va <= vb) { v = va; a++; } else { v = vb; b++; }
        out[k0 + o] = k2f(v);
    }
}

__global__ void __launch_bounds__(RT)
k_sort_radixL() {
    extern __shared__ unsigned su[];
    unsigned* R0 = su;
    unsigned* R1 = su + HALF;
    unsigned* R2 = su + 2 * HALF;
    unsigned* hist = su + 3 * HALF;
    unsigned* tot = hist + NW * 256;
    const int tid = threadIdx.x;
    const int nseg = g_n2b * 128;

    for (int s = blockIdx.x; s < nseg; s += gridDim.x) {
        const int c = g_l2b[s >> 7];
        const int r = s & 127;
        const int d = r & 63;
        const int m = g_m[c], P = g_P[c];
        float* seg = ((r >> 6) ? g_tg : g_xg) + (size_t)g_off[c] * DIMS + (size_t)d * P;

        if (m <= HALF) {
            const int n = ((m + RT - 1) / RT) * RT;
            for (int i = tid; i < n; i += RT)
                R0[i] = (i < m) ? f2k(seg[i]) : 0xFFFFFFFFu;
            __syncthreads();
            radix_sort_n(R0, R2, hist, tot, n);
            for (int i = tid; i < m; i += RT) seg[i] = k2f(R0[i]);
        } else {
            for (int i = tid; i < HALF; i += RT)
                R0[i] = (i < m) ? f2k(seg[i]) : 0xFFFFFFFFu;
            __syncthreads();
            radix_sort_n(R0, R2, hist, tot, HALF);
            for (int i = tid; i < HALF; i += RT) {
                int j = HALF + i;
                R1[i] = (j < m) ? f2k(seg[j]) : 0xFFFFFFFFu;
            }
            __syncthreads();
            radix_sort_n(R1, R2, hist, tot, HALF);
            merge_write(R0, R1, seg);
        }
        __syncthreads();
    }
}

// Global bitonic fallback, P > 32768 (safety; expected empty)
__global__ void __launch_bounds__(1024)
k_sort_t3() {
    const int T = blockDim.x, tid = threadIdx.x;
    const int nseg = g_n3 * 128;
    for (int s = blockIdx.x; s < nseg; s += gridDim.x) {
        const int c = g_l3[s >> 7];
        const int r = s & 127;
        const int d = r & 63;
        const int m = g_m[c], P = g_P[c];
        float* seg = ((r >> 6) ? g_tg : g_xg) + (size_t)g_off[c] * DIMS + (size_t)d * P;
        for (int j = m + tid; j < P; j += T) seg[j] = BIGF;
        __syncthreads();
        for (int k = 2; k <= P; k <<= 1) {
            for (int j = k >> 1; j > 0; j >>= 1) {
                for (int idx = tid; idx < P; idx += T) {
                    int l = idx ^ j;
                    if (l > idx) {
                        float a = seg[idx], b = seg[l];
                        bool up = ((idx & k) == 0);
                        if ((a > b) == up) { seg[idx] = b; seg[l] = a; }
                    }
                }
                __syncthreads();
            }
        }
        __syncthreads();
    }
}

// ----------------------------------------------------------------------------
// K5: Wasserstein partials per (cluster, dim)
// ----------------------------------------------------------------------------
__global__ void k_diff() {
    const int cd = blockIdx.x;
    const int c = cd >> 6, d = cd & 63;
    const int m = g_m[c];
    if (m < 1) { if (threadIdx.x == 0) g_part[cd] = 0.0f; return; }
    const int P = g_P[c];
    const size_t base = (size_t)g_off[c] * DIMS + (size_t)d * P;

    float s = 0.0f;
    for (int j = threadIdx.x; j < m; j += blockDim.x)
        s += fabsf(g_xg[base + j] - g_tg[base + j]);

    __shared__ float red[256];
    red[threadIdx.x] = s;
    __syncthreads();
    for (int o = blockDim.x >> 1; o > 0; o >>= 1) {
        if (threadIdx.x < o) red[threadIdx.x] += red[threadIdx.x + o];
        __syncthreads();
    }
    if (threadIdx.x == 0)
        g_part[cd] = red[0] / ((float)m * DIMS);
}

// ----------------------------------------------------------------------------
// K6: finalize
// ----------------------------------------------------------------------------
__global__ void k_final(const float* __restrict__ ftgt, float* out) {
    const int tid = threadIdx.x;
    __shared__ double red[256];

    double s = 0.0;
    for (int i = tid; i < KD; i += 256) s += (double)g_part[i];
    red[tid] = s;
    __syncthreads();
    for (int o = 128; o > 0; o >>= 1) {
        if (tid < o) red[tid] += red[tid + o];
        __syncthreads();
    }

    if (tid == 0) {
        float lf = 0.0f;
        for (int c = 0; c < KCL; c++) {
            float diff = g_fill[c] * (1.0f / N_PTS) - ftgt[c];
            lf += diff * diff;
        }
        out[0] = (float)((double)(lf / KCL) + red[0]);
    }
}

// ----------------------------------------------------------------------------
// Launch
// ----------------------------------------------------------------------------
extern "C" void kernel_launch(void* const* d_in, const int* in_sizes, int n_in,
                              void* d_out, int out_size) {
    const float* x     = (const float*)d_in[0];
    const float* tgt   = (const float*)d_in[1];
    const float* cc    = (const float*)d_in[2];
    const int*   predt = (const int*)d_in[3];
    const float* ftgt  = (const float*)d_in[4];
    float* out = (float*)d_out;

    const int ASSIGN_SMEM = (KCL * DIMS + KCL + KCL * ABLK + KCL) * 4 + KCL * 8;
    const int MERGE_SMEM = 2 * MBUF * 4;                     // 67584 B
    const int RADL_SMEM = (3 * HALF + NW * 256 + 256) * 4;   // 214016 B
    cudaFuncSetAttribute(k_assign,
                         cudaFuncAttributeMaxDynamicSharedMemorySize, ASSIGN_SMEM);
    cudaFuncSetAttribute(k_sort_merge,
                         cudaFuncAttributeMaxDynamicSharedMemorySize, MERGE_SMEM);
    cudaFuncSetAttribute(k_sort_radixL,
                         cudaFuncAttributeMaxDynamicSharedMemorySize, RADL_SMEM);

    k_assign<<<NBLK, ABLK, ASSIGN_SMEM>>>(x, cc, predt);     // 0
    k_scan1<<<KCL, NBLK>>>();                                // 1
    k_scatter2<<<NBLK, ABLK>>>(x, tgt, predt);               // 2
    k_sort_merge<<<444, MT, MERGE_SMEM>>>();                 // 3 <- ncu (verify pass cut)
    k_sort_warpA<<<2048, 256>>>();                           // 4
    k_sort_warpB<<<1024, 256>>>();                           // 5
    k_sort_radixL<<<148, RT, RADL_SMEM>>>();                 // 6
    k_sort_t3<<<148, 1024>>>();                              // 7
    k_diff<<<KD, 256>>>();                                   // 8
    k_final<<<1, 256>>>(ftgt, out);                          // 9
}